// round 15
// baseline (speedup 1.0000x reference)
#include <cuda_runtime.h>
#include <cuda_fp16.h>
#include <cstdint>

#define Bd 4
#define Td 2048
#define Cd 1024
#define Md (Bd*Td)
#define QSC 0.18033688011112042f   // log2(e)/8

__device__ __half g_ln [Md*Cd];
__device__ __half g_y  [Md*Cd];
__device__ __half g_x1h[Md*Cd];         // residual stream after attn (f16)
__device__ __half g_h  [Md*4*Cd];
__device__ __half g_w  [12*1024*1024];
__device__ __half g_q  [64*Td*64];
__device__ __half g_kp [64*Td*64];
__device__ __half g_vp [64*Td*64];

__device__ __forceinline__ uint32_t packh(float lo, float hi){
    __half2 h = __floats2half2_rn(lo, hi);
    return *(uint32_t*)&h;
}
__device__ __forceinline__ uint32_t exp2u(uint32_t s){
    __half2 h = h2exp2(*(__half2*)&s);
    return *(uint32_t*)&h;
}
__device__ __forceinline__ float gelu_f(float x){
    float u = 0.7978845608028654f * (x + 0.044715f * x * x * x);
    return 0.5f * x * (1.0f + tanhf(u));
}
__device__ __forceinline__ void cp_async16(void* smem, const void* gmem){
    uint32_t s = (uint32_t)__cvta_generic_to_shared(smem);
    asm volatile("cp.async.cg.shared.global [%0], [%1], 16;\n" :: "r"(s), "l"(gmem));
}
__device__ __forceinline__ void cp_commit(){ asm volatile("cp.async.commit_group;\n"); }
template<int N> __device__ __forceinline__ void cp_wait(){
    asm volatile("cp.async.wait_group %0;\n" :: "n"(N));
}
__device__ __forceinline__ void mma16h(float c[4], const uint32_t a[4],
                                       uint32_t b0, uint32_t b1){
    asm volatile("mma.sync.aligned.m16n8k16.row.col.f32.f16.f16.f32 "
      "{%0,%1,%2,%3},{%4,%5,%6,%7},{%8,%9},{%0,%1,%2,%3};"
      : "+f"(c[0]), "+f"(c[1]), "+f"(c[2]), "+f"(c[3])
      : "r"(a[0]), "r"(a[1]), "r"(a[2]), "r"(a[3]), "r"(b0), "r"(b1));
}
__device__ __forceinline__ void mma16hh(uint32_t c[2], const uint32_t a[4],
                                        uint32_t b0, uint32_t b1){
    asm volatile("mma.sync.aligned.m16n8k16.row.col.f16.f16.f16.f16 "
      "{%0,%1},{%2,%3,%4,%5},{%6,%7},{%0,%1};"
      : "+r"(c[0]), "+r"(c[1])
      : "r"(a[0]), "r"(a[1]), "r"(a[2]), "r"(a[3]), "r"(b0), "r"(b1));
}
__device__ __forceinline__ void ldsm4(uint32_t& r0, uint32_t& r1, uint32_t& r2,
                                      uint32_t& r3, uint32_t a){
    asm volatile("ldmatrix.sync.aligned.m8n8.x4.shared.b16 {%0,%1,%2,%3}, [%4];"
                 : "=r"(r0), "=r"(r1), "=r"(r2), "=r"(r3) : "r"(a));
}
__device__ __forceinline__ void ldsm4t(uint32_t& r0, uint32_t& r1, uint32_t& r2,
                                       uint32_t& r3, uint32_t a){
    asm volatile("ldmatrix.sync.aligned.m8n8.x4.trans.shared.b16 {%0,%1,%2,%3}, [%4];"
                 : "=r"(r0), "=r"(r1), "=r"(r2), "=r"(r3) : "r"(a));
}

// ---------------- weight conversion ----------------
__global__ __launch_bounds__(256) void cvtw_all(
    const float* __restrict__ wa, const float* __restrict__ wp,
    const float* __restrict__ wf, const float* __restrict__ wm,
    __half* __restrict__ d)
{
    const int M1 = 1024*1024;
    int i = (blockIdx.x * 256 + threadIdx.x) * 4;
    const float* s;
    int off;
    if      (i <  3*M1){ s = wa; off = 0;    }
    else if (i <  4*M1){ s = wp; off = 3*M1; }
    else if (i <  8*M1){ s = wf; off = 4*M1; }
    else               { s = wm; off = 8*M1; }
    float4 v = *(const float4*)(s + (i - off));
    *(uint2*)(d + i) = make_uint2(packh(v.x, v.y), packh(v.z, v.w));
}

// ---------------- LayerNorm: warp per row; fp32-in and f16-in variants -----
__global__ __launch_bounds__(256) void ln_kernel(const float* __restrict__ in,
                                                 __half* __restrict__ out){
    const int wid = threadIdx.x >> 5, lane = threadIdx.x & 31;
    const int row = blockIdx.x * 8 + wid;
    const float4* src = (const float4*)(in + (size_t)row * Cd);
    float4 v[8];
    float s = 0.f;
    #pragma unroll
    for (int i = 0; i < 8; i++){
        v[i] = src[i * 32 + lane];
        s += v[i].x + v[i].y + v[i].z + v[i].w;
    }
    #pragma unroll
    for (int o = 16; o > 0; o >>= 1) s += __shfl_xor_sync(~0u, s, o);
    float mean = s * (1.0f/1024.0f);
    float ss = 0.f;
    #pragma unroll
    for (int i = 0; i < 8; i++){
        v[i].x -= mean; v[i].y -= mean; v[i].z -= mean; v[i].w -= mean;
        ss += v[i].x*v[i].x + v[i].y*v[i].y + v[i].z*v[i].z + v[i].w*v[i].w;
    }
    #pragma unroll
    for (int o = 16; o > 0; o >>= 1) ss += __shfl_xor_sync(~0u, ss, o);
    float rstd = rsqrtf(ss * (1.0f/1024.0f) + 1e-10f);
    uint2* dst = (uint2*)(out + (size_t)row * Cd);
    #pragma unroll
    for (int i = 0; i < 8; i++)
        dst[i * 32 + lane] = make_uint2(packh(v[i].x*rstd, v[i].y*rstd),
                                        packh(v[i].z*rstd, v[i].w*rstd));
}

__global__ __launch_bounds__(256) void ln_kernel_h(const __half* __restrict__ in,
                                                   __half* __restrict__ out){
    const int wid = threadIdx.x >> 5, lane = threadIdx.x & 31;
    const int row = blockIdx.x * 8 + wid;
    const uint2* src = (const uint2*)(in + (size_t)row * Cd);
    float4 v[8];
    float s = 0.f;
    #pragma unroll
    for (int i = 0; i < 8; i++){
        uint2 u = src[i * 32 + lane];
        float2 a = __half22float2(*(__half2*)&u.x);
        float2 b = __half22float2(*(__half2*)&u.y);
        v[i] = make_float4(a.x, a.y, b.x, b.y);
        s += v[i].x + v[i].y + v[i].z + v[i].w;
    }
    #pragma unroll
    for (int o = 16; o > 0; o >>= 1) s += __shfl_xor_sync(~0u, s, o);
    float mean = s * (1.0f/1024.0f);
    float ss = 0.f;
    #pragma unroll
    for (int i = 0; i < 8; i++){
        v[i].x -= mean; v[i].y -= mean; v[i].z -= mean; v[i].w -= mean;
        ss += v[i].x*v[i].x + v[i].y*v[i].y + v[i].z*v[i].z + v[i].w*v[i].w;
    }
    #pragma unroll
    for (int o = 16; o > 0; o >>= 1) ss += __shfl_xor_sync(~0u, ss, o);
    float rstd = rsqrtf(ss * (1.0f/1024.0f) + 1e-10f);
    uint2* dst = (uint2*)(out + (size_t)row * Cd);
    #pragma unroll
    for (int i = 0; i < 8; i++)
        dst[i * 32 + lane] = make_uint2(packh(v[i].x*rstd, v[i].y*rstd),
                                        packh(v[i].z*rstd, v[i].w*rstd));
}

// ---------------- f16 GEMM ----------------
// mode 1: gelu -> f16 out. mode 2: qkv scatter.
// mode 3: f16 out + float res. mode 4: float out + f16 res.
__global__ __launch_bounds__(256) void gemm_f16(
    const __half* __restrict__ A, const __half* __restrict__ W,
    const float* __restrict__ bias, const float* __restrict__ resf,
    const __half* __restrict__ resh,
    void* outp, int M, int N, int K, int mode)
{
    extern __shared__ char smc[];
    const int bm = blockIdx.y * 128, bn = blockIdx.x * 128;
    const int tid = threadIdx.x, wid = tid >> 5, lane = tid & 31;
    const int wm = (wid >> 2) * 64, wn = (wid & 3) * 32;
    const int g = lane >> 2, tg = lane & 3;
    const int l7 = lane & 7, kc = (lane >> 3) & 1, hc = (lane >> 4) & 1;
    const uint32_t smb = (uint32_t)__cvta_generic_to_shared(smc);

    float acc[4][4][4];
    #pragma unroll
    for (int i = 0; i < 4; i++)
        #pragma unroll
        for (int j = 0; j < 4; j++)
            #pragma unroll
            for (int k = 0; k < 4; k++) acc[i][j][k] = 0.f;

    const int nt = K >> 6;
    auto load_st = [&](int kt, int st){
        char* base = smc + st * 32768;
        #pragma unroll
        for (int i = 0; i < 4; i++){
            int x = tid + i * 256;
            int r = x >> 3, pc = x & 7;
            int sw = ((pc ^ (r & 7)) << 4);
            cp_async16(base + r*128 + sw,         A + (size_t)(bm + r)*K + kt*64 + pc*8);
            cp_async16(base + 16384 + r*128 + sw, W + (size_t)(bn + r)*K + kt*64 + pc*8);
        }
    };

    load_st(0, 0); cp_commit();
    load_st(1, 1); cp_commit();

    for (int kt = 0; kt < nt; kt++){
        cp_wait<1>();
        __syncthreads();
        if (kt + 2 < nt){ load_st(kt + 2, (kt + 2) % 3); }
        cp_commit();
        const uint32_t sa = smb + (uint32_t)((kt % 3) * 32768);
        const uint32_t sb = sa + 16384;
        #pragma unroll
        for (int ks = 0; ks < 4; ks++){
            const uint32_t co = (uint32_t)(((2*ks + hc) ^ l7) << 4);
            uint32_t a[4][4];
            #pragma unroll
            for (int mf = 0; mf < 4; mf++)
                ldsm4(a[mf][0], a[mf][1], a[mf][2], a[mf][3],
                      sa + (uint32_t)((wm + mf*16 + l7 + 8*kc) * 128) + co);
            #pragma unroll
            for (int pr = 0; pr < 2; pr++){
                uint32_t r0, r1, r2, r3;
                ldsm4(r0, r1, r2, r3,
                      sb + (uint32_t)((wn + pr*16 + l7 + 8*kc) * 128) + co);
                #pragma unroll
                for (int mf = 0; mf < 4; mf++){
                    mma16h(acc[mf][2*pr  ], a[mf], r0, r2);
                    mma16h(acc[mf][2*pr+1], a[mf], r1, r3);
                }
            }
        }
    }

    if (mode == 2){
        __syncthreads();
        __half* stg = (__half*)smc;
        const float qsc = (bn < 1024) ? QSC : 1.0f;
        #pragma unroll
        for (int mf = 0; mf < 4; mf++){
            #pragma unroll
            for (int nf = 0; nf < 4; nf++){
                int rl = wm + mf * 16 + g;
                int cl = wn + nf * 8 + 2 * tg;
                int col = bn + cl;
                float bx = bias[col], by = bias[col + 1];
                *(uint32_t*)&stg[rl * 128 + cl] =
                    packh((acc[mf][nf][0] + bx) * qsc, (acc[mf][nf][1] + by) * qsc);
                *(uint32_t*)&stg[(rl + 8) * 128 + cl] =
                    packh((acc[mf][nf][2] + bx) * qsc, (acc[mf][nf][3] + by) * qsc);
            }
        }
        __syncthreads();
        #pragma unroll
        for (int i = 0; i < 8; i++){
            int x = tid + i * 256;
            int r = x >> 4, c16 = x & 15;
            uint4 v = ((const uint4*)stg)[x];
            int row = bm + r, t = row & 2047, b = row >> 11;
            int col = bn + c16 * 8;
            if (col < 1024){
                int h = col >> 6, d = col & 63;
                *(uint4*)(g_q + ((size_t)(b*16 + h)*Td + t)*64 + d) = v;
            } else if (col < 2048){
                int c2 = col - 1024, h = c2 >> 6, d = c2 & 63;
                int dc = (d >> 3) ^ (t & 7);
                *(uint4*)((char*)g_kp + ((size_t)(b*16 + h)*Td + t)*128 + dc*16) = v;
            } else {
                int c2 = col - 2048, h = c2 >> 6, d = c2 & 63;
                int dc = (d >> 3) ^ (t & 7);
                *(uint4*)((char*)g_vp + ((size_t)(b*16 + h)*Td + t)*128 + dc*16) = v;
            }
        }
        return;
    }

    #pragma unroll
    for (int mf = 0; mf < 4; mf++){
        #pragma unroll
        for (int nf = 0; nf < 4; nf++){
            int row = bm + wm + mf * 16 + g;
            int col = bn + wn + nf * 8 + 2 * tg;
            float bx = bias[col], by = bias[col + 1];
            float o0 = acc[mf][nf][0] + bx, o1 = acc[mf][nf][1] + by;
            float o2 = acc[mf][nf][2] + bx, o3 = acc[mf][nf][3] + by;
            if (mode == 1){
                __half* out = (__half*)outp;
                *(uint32_t*)(out + (size_t)row * N + col)       = packh(gelu_f(o0), gelu_f(o1));
                *(uint32_t*)(out + (size_t)(row + 8) * N + col) = packh(gelu_f(o2), gelu_f(o3));
            } else if (mode == 3){
                float2 r0 = *(const float2*)(resf + (size_t)row * N + col);
                float2 r1 = *(const float2*)(resf + (size_t)(row + 8) * N + col);
                __half* out = (__half*)outp;
                *(uint32_t*)(out + (size_t)row * N + col)       = packh(o0 + r0.x, o1 + r0.y);
                *(uint32_t*)(out + (size_t)(row + 8) * N + col) = packh(o2 + r1.x, o3 + r1.y);
            } else {  // mode 4
                uint32_t u0 = *(const uint32_t*)(resh + (size_t)row * N + col);
                uint32_t u1 = *(const uint32_t*)(resh + (size_t)(row + 8) * N + col);
                float2 r0 = __half22float2(*(__half2*)&u0);
                float2 r1 = __half22float2(*(__half2*)&u1);
                float* out = (float*)outp;
                *(float2*)(out + (size_t)row * N + col)       = make_float2(o0 + r0.x, o1 + r0.y);
                *(float2*)(out + (size_t)(row + 8) * N + col) = make_float2(o2 + r1.x, o3 + r1.y);
            }
        }
    }
}

// ---------------- Flash attention v9: 3-stage ring, single sync/tile -------
__global__ __launch_bounds__(256, 2) void attn_tc(__half* __restrict__ y){
    extern __shared__ char asm_[];            // 3 stages x (K 16KB + V 16KB)
    const int qt = (int)gridDim.x - 1 - (int)blockIdx.x;
    const int bh = blockIdx.y;
    const int b  = bh >> 4, h = bh & 15;
    const int q0 = qt * 128;
    const int tid = threadIdx.x, wid = tid >> 5, lane = tid & 31;
    const int g = lane >> 2, tg = lane & 3;
    const int wrow = wid * 16;
    const int l7 = lane & 7, kc = (lane >> 3) & 1, hc = (lane >> 4) & 1;
    const uint32_t smb = (uint32_t)__cvta_generic_to_shared(asm_);
    const uint32_t ONES = 0x3C003C00u;
    const uint32_t NINF_LO = 0x0000FBFFu;
    const uint32_t NINF_HI = 0xFBFF0000u;

    uint32_t aq[4][4];
    {
        const __half* q0p = g_q + ((size_t)bh*Td + q0 + wrow + g)*64;
        const __half* q1p = q0p + 8*64;
        #pragma unroll
        for (int kf = 0; kf < 4; kf++){
            aq[kf][0] = *(const uint32_t*)(q0p + kf*16 +     2*tg);
            aq[kf][1] = *(const uint32_t*)(q1p + kf*16 +     2*tg);
            aq[kf][2] = *(const uint32_t*)(q0p + kf*16 + 8 + 2*tg);
            aq[kf][3] = *(const uint32_t*)(q1p + kf*16 + 8 + 2*tg);
        }
    }

    float oacc[8][4];
    #pragma unroll
    for (int i = 0; i < 8; i++)
        #pragma unroll
        for (int j = 0; j < 4; j++) oacc[i][j] = 0.f;
    float lacc[4] = {0.f, 0.f, 0.f, 0.f};

    const char* kpb = (const char*)(g_kp + (size_t)bh * Td * 64);
    const char* vpb = (const char*)(g_vp + (size_t)bh * Td * 64);
    auto load_tile = [&](int kt2, int s){
        const char* ks = kpb + (size_t)kt2 * 16384;
        const char* vs = vpb + (size_t)kt2 * 16384;
        char* kd = asm_ + s * 32768;
        char* vd = kd + 16384;
        #pragma unroll
        for (int i = 0; i < 4; i++){
            int x = (tid + i * 256) * 16;
            cp_async16(kd + x, ks + x);
            cp_async16(vd + x, vs + x);
        }
    };

    const int nk2 = qt + 1;
    load_tile(0, 0); cp_commit();
    if (nk2 > 1){ load_tile(1, 1); } cp_commit();

    for (int kt2 = 0; kt2 < nk2; kt2++){
        cp_wait<1>();
        __syncthreads();
        if (kt2 + 2 < nk2){ load_tile(kt2 + 2, (kt2 + 2) % 3); }
        cp_commit();
        const uint32_t stgb = smb + (uint32_t)((kt2 % 3) * 32768);

        #pragma unroll
        for (int sub = 0; sub < 2; sub++){
            const int key0 = kt2 * 128 + sub * 64;
            if (key0 <= q0 + wrow + 15){
                const uint32_t kbuf = stgb + (uint32_t)(sub * 8192);
                const uint32_t vbuf = kbuf + 16384;

                uint32_t sacc16[8][2];
                #pragma unroll
                for (int i = 0; i < 8; i++){ sacc16[i][0] = 0; sacc16[i][1] = 0; }
                #pragma unroll
                for (int p = 0; p < 4; p++){
                    const uint32_t krb = kbuf + (uint32_t)((p*16 + 8*hc + l7) * 128);
                    #pragma unroll
                    for (int kf = 0; kf < 4; kf++){
                        uint32_t r0, r1, r2, r3;
                        ldsm4(r0, r1, r2, r3, krb + (uint32_t)(((2*kf + kc) ^ l7) << 4));
                        mma16hh(sacc16[2*p  ], aq[kf], r0, r1);
                        mma16hh(sacc16[2*p+1], aq[kf], r2, r3);
                    }
                }

                if (key0 + 63 > q0 + wrow){
                    const int row0 = q0 + wrow + g, row1 = row0 + 8;
                    #pragma unroll
                    for (int nf = 0; nf < 8; nf++){
                        int c0 = key0 + nf*8 + 2*tg, c1 = c0 + 1;
                        uint32_t v0 = sacc16[nf][0], v1 = sacc16[nf][1];
                        if (c0 > row0) v0 = (v0 & 0xFFFF0000u) | NINF_LO;
                        if (c1 > row0) v0 = (v0 & 0x0000FFFFu) | NINF_HI;
                        if (c0 > row1) v1 = (v1 & 0xFFFF0000u) | NINF_LO;
                        if (c1 > row1) v1 = (v1 & 0x0000FFFFu) | NINF_HI;
                        sacc16[nf][0] = v0; sacc16[nf][1] = v1;
                    }
                }

                uint32_t ap[4][4];
                #pragma unroll
                for (int kf = 0; kf < 4; kf++){
                    ap[kf][0] = exp2u(sacc16[2*kf  ][0]);
                    ap[kf][1] = exp2u(sacc16[2*kf  ][1]);
                    ap[kf][2] = exp2u(sacc16[2*kf+1][0]);
                    ap[kf][3] = exp2u(sacc16[2*kf+1][1]);
                }

                #pragma unroll
                for (int kf = 0; kf < 4; kf++){
                    mma16h(lacc, ap[kf], ONES, ONES);
                    const uint32_t vrb = vbuf + (uint32_t)((16*kf + l7 + 8*kc) * 128);
                    #pragma unroll
                    for (int p = 0; p < 4; p++){
                        uint32_t r0, r1, r2, r3;
                        ldsm4t(r0, r1, r2, r3, vrb + (uint32_t)(((2*p + hc) ^ l7) << 4));
                        mma16h(oacc[2*p  ], ap[kf], r0, r1);
                        mma16h(oacc[2*p+1], ap[kf], r2, r3);
                    }
                }
            }
        }
    }

    float inv0 = 1.0f / lacc[0], inv1 = 1.0f / lacc[2];
    __half* yb = y + ((size_t)(b*Td + q0)) * Cd + h * 64;
    #pragma unroll
    for (int nf = 0; nf < 8; nf++){
        int col = nf*8 + 2*tg;
        *(uint32_t*)(yb + (size_t)(wrow + g    ) * Cd + col) =
            packh(oacc[nf][0]*inv0, oacc[nf][1]*inv0);
        *(uint32_t*)(yb + (size_t)(wrow + g + 8) * Cd + col) =
            packh(oacc[nf][2]*inv1, oacc[nf][3]*inv1);
    }
}

// ---------------------------------------------------------------------------
extern "C" void kernel_launch(void* const* d_in, const int* in_sizes, int n_in,
                              void* d_out, int out_size){
    const float* x          = (const float*)d_in[0];
    const float* w_attn     = (const float*)d_in[1];
    const float* b_attn     = (const float*)d_in[2];
    const float* w_proj     = (const float*)d_in[3];
    const float* b_proj     = (const float*)d_in[4];
    const float* w_fc       = (const float*)d_in[5];
    const float* b_fc       = (const float*)d_in[6];
    const float* w_mlp_proj = (const float*)d_in[7];
    const float* b_mlp_proj = (const float*)d_in[8];
    float* out = (float*)d_out;

    __half *ln_p, *y_p, *h_p, *w_p, *x1h_p;
    cudaGetSymbolAddress((void**)&ln_p,  g_ln);
    cudaGetSymbolAddress((void**)&y_p,   g_y);
    cudaGetSymbolAddress((void**)&x1h_p, g_x1h);
    cudaGetSymbolAddress((void**)&h_p,   g_h);
    cudaGetSymbolAddress((void**)&w_p,   g_w);

    const int gemm_smem = 3 * 32768;   // 96KB
    const int attn_smem = 3 * 32768;   // 96KB
    cudaFuncSetAttribute(gemm_f16, cudaFuncAttributeMaxDynamicSharedMemorySize, gemm_smem);
    cudaFuncSetAttribute(attn_tc,  cudaFuncAttributeMaxDynamicSharedMemorySize, attn_smem);

    const int M1 = 1024*1024;
    cvtw_all<<<12*M1/1024, 256>>>(w_attn, w_proj, w_fc, w_mlp_proj, w_p);

    // 1. ln1
    ln_kernel<<<Md/8, 256>>>(x, ln_p);
    // 2. qkv (staged coalesced scatter -> g_q/g_kp/g_vp)
    gemm_f16<<<dim3(3072/128, Md/128), 256, gemm_smem>>>(ln_p, w_p, b_attn, nullptr,
                                                         nullptr, nullptr, Md, 3072, 1024, 2);
    // 3. attention
    attn_tc<<<dim3(Td/128, 64), 256, attn_smem>>>(y_p);
    // 4. x1 = proj(y) + x  (f16 out, float res)
    gemm_f16<<<dim3(1024/128, Md/128), 256, gemm_smem>>>(y_p, w_p + 3*M1, b_proj, x,
                                                         nullptr, x1h_p, Md, 1024, 1024, 3);
    // 5. ln2 (f16 input)
    ln_kernel_h<<<Md/8, 256>>>(x1h_p, ln_p);
    // 6. fc + gelu -> h (f16)
    gemm_f16<<<dim3(4096/128, Md/128), 256, gemm_smem>>>(ln_p, w_p + 4*M1, b_fc, nullptr,
                                                         nullptr, h_p, Md, 4096, 1024, 1);
    // 7. out = mlp(h) + x1  (float out, f16 res)
    gemm_f16<<<dim3(1024/128, Md/128), 256, gemm_smem>>>(h_p, w_p + 8*M1, b_mlp_proj, nullptr,
                                                         x1h_p, out, Md, 1024, 4096, 4);
}

// round 16
// speedup vs baseline: 1.0092x; 1.0092x over previous
#include <cuda_runtime.h>
#include <cuda_fp16.h>
#include <cstdint>

#define Bd 4
#define Td 2048
#define Cd 1024
#define Md (Bd*Td)
#define QSC 0.18033688011112042f   // log2(e)/8

__device__ __half g_ln[Md*Cd];
__device__ __half g_y [Md*Cd];
__device__ float  g_x1[Md*Cd];
__device__ __half g_h [Md*4*Cd];
__device__ __half g_w [12*1024*1024];
__device__ __half g_q [64*Td*64];
__device__ __half g_kp[64*Td*64];
__device__ __half g_vp[64*Td*64];

__device__ __forceinline__ uint32_t packh(float lo, float hi){
    __half2 h = __floats2half2_rn(lo, hi);
    return *(uint32_t*)&h;
}
__device__ __forceinline__ uint32_t exp2u(uint32_t s){
    __half2 h = h2exp2(*(__half2*)&s);
    return *(uint32_t*)&h;
}
__device__ __forceinline__ float gelu_f(float x){
    float u = 0.7978845608028654f * (x + 0.044715f * x * x * x);
    return 0.5f * x * (1.0f + tanhf(u));
}
__device__ __forceinline__ void cp_async16(void* smem, const void* gmem){
    uint32_t s = (uint32_t)__cvta_generic_to_shared(smem);
    asm volatile("cp.async.cg.shared.global [%0], [%1], 16;\n" :: "r"(s), "l"(gmem));
}
__device__ __forceinline__ void cp_commit(){ asm volatile("cp.async.commit_group;\n"); }
template<int N> __device__ __forceinline__ void cp_wait(){
    asm volatile("cp.async.wait_group %0;\n" :: "n"(N));
}
__device__ __forceinline__ void mma16h(float c[4], const uint32_t a[4],
                                       uint32_t b0, uint32_t b1){
    asm volatile("mma.sync.aligned.m16n8k16.row.col.f32.f16.f16.f32 "
      "{%0,%1,%2,%3},{%4,%5,%6,%7},{%8,%9},{%0,%1,%2,%3};"
      : "+f"(c[0]), "+f"(c[1]), "+f"(c[2]), "+f"(c[3])
      : "r"(a[0]), "r"(a[1]), "r"(a[2]), "r"(a[3]), "r"(b0), "r"(b1));
}
__device__ __forceinline__ void mma16hh(uint32_t c[2], const uint32_t a[4],
                                        uint32_t b0, uint32_t b1){
    asm volatile("mma.sync.aligned.m16n8k16.row.col.f16.f16.f16.f16 "
      "{%0,%1},{%2,%3,%4,%5},{%6,%7},{%0,%1};"
      : "+r"(c[0]), "+r"(c[1])
      : "r"(a[0]), "r"(a[1]), "r"(a[2]), "r"(a[3]), "r"(b0), "r"(b1));
}
__device__ __forceinline__ void ldsm4(uint32_t& r0, uint32_t& r1, uint32_t& r2,
                                      uint32_t& r3, uint32_t a){
    asm volatile("ldmatrix.sync.aligned.m8n8.x4.shared.b16 {%0,%1,%2,%3}, [%4];"
                 : "=r"(r0), "=r"(r1), "=r"(r2), "=r"(r3) : "r"(a));
}
__device__ __forceinline__ void ldsm4t(uint32_t& r0, uint32_t& r1, uint32_t& r2,
                                       uint32_t& r3, uint32_t a){
    asm volatile("ldmatrix.sync.aligned.m8n8.x4.trans.shared.b16 {%0,%1,%2,%3}, [%4];"
                 : "=r"(r0), "=r"(r1), "=r"(r2), "=r"(r3) : "r"(a));
}

// ---------------- weight conversion ----------------
__global__ __launch_bounds__(256) void cvtw_all(
    const float* __restrict__ wa, const float* __restrict__ wp,
    const float* __restrict__ wf, const float* __restrict__ wm,
    __half* __restrict__ d)
{
    const int M1 = 1024*1024;
    int i = (blockIdx.x * 256 + threadIdx.x) * 4;
    const float* s;
    int off;
    if      (i <  3*M1){ s = wa; off = 0;    }
    else if (i <  4*M1){ s = wp; off = 3*M1; }
    else if (i <  8*M1){ s = wf; off = 4*M1; }
    else               { s = wm; off = 8*M1; }
    float4 v = *(const float4*)(s + (i - off));
    *(uint2*)(d + i) = make_uint2(packh(v.x, v.y), packh(v.z, v.w));
}

// ---------------- LayerNorm: one warp per row ----------------
__global__ __launch_bounds__(256) void ln_kernel(const float* __restrict__ in,
                                                 __half* __restrict__ out){
    const int wid = threadIdx.x >> 5, lane = threadIdx.x & 31;
    const int row = blockIdx.x * 8 + wid;
    const float4* src = (const float4*)(in + (size_t)row * Cd);
    float4 v[8];
    float s = 0.f;
    #pragma unroll
    for (int i = 0; i < 8; i++){
        v[i] = src[i * 32 + lane];
        s += v[i].x + v[i].y + v[i].z + v[i].w;
    }
    #pragma unroll
    for (int o = 16; o > 0; o >>= 1) s += __shfl_xor_sync(~0u, s, o);
    float mean = s * (1.0f/1024.0f);
    float ss = 0.f;
    #pragma unroll
    for (int i = 0; i < 8; i++){
        v[i].x -= mean; v[i].y -= mean; v[i].z -= mean; v[i].w -= mean;
        ss += v[i].x*v[i].x + v[i].y*v[i].y + v[i].z*v[i].z + v[i].w*v[i].w;
    }
    #pragma unroll
    for (int o = 16; o > 0; o >>= 1) ss += __shfl_xor_sync(~0u, ss, o);
    float rstd = rsqrtf(ss * (1.0f/1024.0f) + 1e-10f);
    uint2* dst = (uint2*)(out + (size_t)row * Cd);
    #pragma unroll
    for (int i = 0; i < 8; i++)
        dst[i * 32 + lane] = make_uint2(packh(v[i].x*rstd, v[i].y*rstd),
                                        packh(v[i].z*rstd, v[i].w*rstd));
}

// ---------------- f16 GEMM (R14-proven: modes 0/1/2) ----------------
__global__ __launch_bounds__(256) void gemm_f16(
    const __half* __restrict__ A, const __half* __restrict__ W,
    const float* __restrict__ bias, const float* __restrict__ res,
    void* outp, int M, int N, int K, int mode)
{
    extern __shared__ char smc[];
    const int bm = blockIdx.y * 128, bn = blockIdx.x * 128;
    const int tid = threadIdx.x, wid = tid >> 5, lane = tid & 31;
    const int wm = (wid >> 2) * 64, wn = (wid & 3) * 32;
    const int g = lane >> 2, tg = lane & 3;
    const int l7 = lane & 7, kc = (lane >> 3) & 1, hc = (lane >> 4) & 1;
    const uint32_t smb = (uint32_t)__cvta_generic_to_shared(smc);

    float acc[4][4][4];
    #pragma unroll
    for (int i = 0; i < 4; i++)
        #pragma unroll
        for (int j = 0; j < 4; j++)
            #pragma unroll
            for (int k = 0; k < 4; k++) acc[i][j][k] = 0.f;

    const int nt = K >> 6;
    auto load_st = [&](int kt, int st){
        char* base = smc + st * 32768;
        #pragma unroll
        for (int i = 0; i < 4; i++){
            int x = tid + i * 256;
            int r = x >> 3, pc = x & 7;
            int sw = ((pc ^ (r & 7)) << 4);
            cp_async16(base + r*128 + sw,         A + (size_t)(bm + r)*K + kt*64 + pc*8);
            cp_async16(base + 16384 + r*128 + sw, W + (size_t)(bn + r)*K + kt*64 + pc*8);
        }
    };

    load_st(0, 0); cp_commit();
    load_st(1, 1); cp_commit();

    for (int kt = 0; kt < nt; kt++){
        cp_wait<1>();
        __syncthreads();
        if (kt + 2 < nt){ load_st(kt + 2, (kt + 2) % 3); }
        cp_commit();
        const uint32_t sa = smb + (uint32_t)((kt % 3) * 32768);
        const uint32_t sb = sa + 16384;
        #pragma unroll
        for (int ks = 0; ks < 4; ks++){
            const uint32_t co = (uint32_t)(((2*ks + hc) ^ l7) << 4);
            uint32_t a[4][4];
            #pragma unroll
            for (int mf = 0; mf < 4; mf++)
                ldsm4(a[mf][0], a[mf][1], a[mf][2], a[mf][3],
                      sa + (uint32_t)((wm + mf*16 + l7 + 8*kc) * 128) + co);
            #pragma unroll
            for (int pr = 0; pr < 2; pr++){
                uint32_t r0, r1, r2, r3;
                ldsm4(r0, r1, r2, r3,
                      sb + (uint32_t)((wn + pr*16 + l7 + 8*kc) * 128) + co);
                #pragma unroll
                for (int mf = 0; mf < 4; mf++){
                    mma16h(acc[mf][2*pr  ], a[mf], r0, r2);
                    mma16h(acc[mf][2*pr+1], a[mf], r1, r3);
                }
            }
        }
    }

    if (mode == 2){
        __syncthreads();
        __half* stg = (__half*)smc;
        const float qsc = (bn < 1024) ? QSC : 1.0f;
        #pragma unroll
        for (int mf = 0; mf < 4; mf++){
            #pragma unroll
            for (int nf = 0; nf < 4; nf++){
                int rl = wm + mf * 16 + g;
                int cl = wn + nf * 8 + 2 * tg;
                int col = bn + cl;
                float bx = bias[col], by = bias[col + 1];
                *(uint32_t*)&stg[rl * 128 + cl] =
                    packh((acc[mf][nf][0] + bx) * qsc, (acc[mf][nf][1] + by) * qsc);
                *(uint32_t*)&stg[(rl + 8) * 128 + cl] =
                    packh((acc[mf][nf][2] + bx) * qsc, (acc[mf][nf][3] + by) * qsc);
            }
        }
        __syncthreads();
        #pragma unroll
        for (int i = 0; i < 8; i++){
            int x = tid + i * 256;
            int r = x >> 4, c16 = x & 15;
            uint4 v = ((const uint4*)stg)[x];
            int row = bm + r, t = row & 2047, b = row >> 11;
            int col = bn + c16 * 8;
            if (col < 1024){
                int h = col >> 6, d = col & 63;
                *(uint4*)(g_q + ((size_t)(b*16 + h)*Td + t)*64 + d) = v;
            } else if (col < 2048){
                int c2 = col - 1024, h = c2 >> 6, d = c2 & 63;
                int dc = (d >> 3) ^ (t & 7);
                *(uint4*)((char*)g_kp + ((size_t)(b*16 + h)*Td + t)*128 + dc*16) = v;
            } else {
                int c2 = col - 2048, h = c2 >> 6, d = c2 & 63;
                int dc = (d >> 3) ^ (t & 7);
                *(uint4*)((char*)g_vp + ((size_t)(b*16 + h)*Td + t)*128 + dc*16) = v;
            }
        }
        return;
    }

    #pragma unroll
    for (int mf = 0; mf < 4; mf++){
        #pragma unroll
        for (int nf = 0; nf < 4; nf++){
            int row = bm + wm + mf * 16 + g;
            int col = bn + wn + nf * 8 + 2 * tg;
            float bx = bias[col], by = bias[col + 1];
            float o0 = acc[mf][nf][0] + bx, o1 = acc[mf][nf][1] + by;
            float o2 = acc[mf][nf][2] + bx, o3 = acc[mf][nf][3] + by;
            if (mode == 0){
                if (res){
                    float2 r0 = *(const float2*)(res + (size_t)row * N + col);
                    float2 r1 = *(const float2*)(res + (size_t)(row + 8) * N + col);
                    o0 += r0.x; o1 += r0.y; o2 += r1.x; o3 += r1.y;
                }
                float* out = (float*)outp;
                *(float2*)(out + (size_t)row * N + col)       = make_float2(o0, o1);
                *(float2*)(out + (size_t)(row + 8) * N + col) = make_float2(o2, o3);
            } else {
                __half* out = (__half*)outp;
                *(uint32_t*)(out + (size_t)row * N + col)       = packh(gelu_f(o0), gelu_f(o1));
                *(uint32_t*)(out + (size_t)(row + 8) * N + col) = packh(gelu_f(o2), gelu_f(o3));
            }
        }
    }
}

// ---------------- Flash attention v9: 3-stage ring, single sync/tile -------
__global__ __launch_bounds__(256, 2) void attn_tc(__half* __restrict__ y){
    extern __shared__ char asm_[];            // 3 stages x (K 16KB + V 16KB)
    const int qt = (int)gridDim.x - 1 - (int)blockIdx.x;
    const int bh = blockIdx.y;
    const int b  = bh >> 4, h = bh & 15;
    const int q0 = qt * 128;
    const int tid = threadIdx.x, wid = tid >> 5, lane = tid & 31;
    const int g = lane >> 2, tg = lane & 3;
    const int wrow = wid * 16;
    const int l7 = lane & 7, kc = (lane >> 3) & 1, hc = (lane >> 4) & 1;
    const uint32_t smb = (uint32_t)__cvta_generic_to_shared(asm_);
    const uint32_t ONES = 0x3C003C00u;
    const uint32_t NINF_LO = 0x0000FBFFu;
    const uint32_t NINF_HI = 0xFBFF0000u;

    uint32_t aq[4][4];
    {
        const __half* q0p = g_q + ((size_t)bh*Td + q0 + wrow + g)*64;
        const __half* q1p = q0p + 8*64;
        #pragma unroll
        for (int kf = 0; kf < 4; kf++){
            aq[kf][0] = *(const uint32_t*)(q0p + kf*16 +     2*tg);
            aq[kf][1] = *(const uint32_t*)(q1p + kf*16 +     2*tg);
            aq[kf][2] = *(const uint32_t*)(q0p + kf*16 + 8 + 2*tg);
            aq[kf][3] = *(const uint32_t*)(q1p + kf*16 + 8 + 2*tg);
        }
    }

    float oacc[8][4];
    #pragma unroll
    for (int i = 0; i < 8; i++)
        #pragma unroll
        for (int j = 0; j < 4; j++) oacc[i][j] = 0.f;
    float lacc[4] = {0.f, 0.f, 0.f, 0.f};

    const char* kpb = (const char*)(g_kp + (size_t)bh * Td * 64);
    const char* vpb = (const char*)(g_vp + (size_t)bh * Td * 64);
    auto load_tile = [&](int kt2, int s){
        const char* ks = kpb + (size_t)kt2 * 16384;
        const char* vs = vpb + (size_t)kt2 * 16384;
        char* kd = asm_ + s * 32768;
        char* vd = kd + 16384;
        #pragma unroll
        for (int i = 0; i < 4; i++){
            int x = (tid + i * 256) * 16;
            cp_async16(kd + x, ks + x);
            cp_async16(vd + x, vs + x);
        }
    };

    const int nk2 = qt + 1;
    load_tile(0, 0); cp_commit();
    if (nk2 > 1){ load_tile(1, 1); } cp_commit();

    for (int kt2 = 0; kt2 < nk2; kt2++){
        cp_wait<1>();
        __syncthreads();
        if (kt2 + 2 < nk2){ load_tile(kt2 + 2, (kt2 + 2) % 3); }
        cp_commit();
        const uint32_t stgb = smb + (uint32_t)((kt2 % 3) * 32768);

        #pragma unroll
        for (int sub = 0; sub < 2; sub++){
            const int key0 = kt2 * 128 + sub * 64;
            if (key0 <= q0 + wrow + 15){
                const uint32_t kbuf = stgb + (uint32_t)(sub * 8192);
                const uint32_t vbuf = kbuf + 16384;

                uint32_t sacc16[8][2];
                #pragma unroll
                for (int i = 0; i < 8; i++){ sacc16[i][0] = 0; sacc16[i][1] = 0; }
                #pragma unroll
                for (int p = 0; p < 4; p++){
                    const uint32_t krb = kbuf + (uint32_t)((p*16 + 8*hc + l7) * 128);
                    #pragma unroll
                    for (int kf = 0; kf < 4; kf++){
                        uint32_t r0, r1, r2, r3;
                        ldsm4(r0, r1, r2, r3, krb + (uint32_t)(((2*kf + kc) ^ l7) << 4));
                        mma16hh(sacc16[2*p  ], aq[kf], r0, r1);
                        mma16hh(sacc16[2*p+1], aq[kf], r2, r3);
                    }
                }

                if (key0 + 63 > q0 + wrow){
                    const int row0 = q0 + wrow + g, row1 = row0 + 8;
                    #pragma unroll
                    for (int nf = 0; nf < 8; nf++){
                        int c0 = key0 + nf*8 + 2*tg, c1 = c0 + 1;
                        uint32_t v0 = sacc16[nf][0], v1 = sacc16[nf][1];
                        if (c0 > row0) v0 = (v0 & 0xFFFF0000u) | NINF_LO;
                        if (c1 > row0) v0 = (v0 & 0x0000FFFFu) | NINF_HI;
                        if (c0 > row1) v1 = (v1 & 0xFFFF0000u) | NINF_LO;
                        if (c1 > row1) v1 = (v1 & 0x0000FFFFu) | NINF_HI;
                        sacc16[nf][0] = v0; sacc16[nf][1] = v1;
                    }
                }

                uint32_t ap[4][4];
                #pragma unroll
                for (int kf = 0; kf < 4; kf++){
                    ap[kf][0] = exp2u(sacc16[2*kf  ][0]);
                    ap[kf][1] = exp2u(sacc16[2*kf  ][1]);
                    ap[kf][2] = exp2u(sacc16[2*kf+1][0]);
                    ap[kf][3] = exp2u(sacc16[2*kf+1][1]);
                }

                #pragma unroll
                for (int kf = 0; kf < 4; kf++){
                    mma16h(lacc, ap[kf], ONES, ONES);
                    const uint32_t vrb = vbuf + (uint32_t)((16*kf + l7 + 8*kc) * 128);
                    #pragma unroll
                    for (int p = 0; p < 4; p++){
                        uint32_t r0, r1, r2, r3;
                        ldsm4t(r0, r1, r2, r3, vrb + (uint32_t)(((2*p + hc) ^ l7) << 4));
                        mma16h(oacc[2*p  ], ap[kf], r0, r1);
                        mma16h(oacc[2*p+1], ap[kf], r2, r3);
                    }
                }
            }
        }
    }

    float inv0 = 1.0f / lacc[0], inv1 = 1.0f / lacc[2];
    __half* yb = y + ((size_t)(b*Td + q0)) * Cd + h * 64;
    #pragma unroll
    for (int nf = 0; nf < 8; nf++){
        int col = nf*8 + 2*tg;
        *(uint32_t*)(yb + (size_t)(wrow + g    ) * Cd + col) =
            packh(oacc[nf][0]*inv0, oacc[nf][1]*inv0);
        *(uint32_t*)(yb + (size_t)(wrow + g + 8) * Cd + col) =
            packh(oacc[nf][2]*inv1, oacc[nf][3]*inv1);
    }
}

// ---------------------------------------------------------------------------
extern "C" void kernel_launch(void* const* d_in, const int* in_sizes, int n_in,
                              void* d_out, int out_size){
    const float* x          = (const float*)d_in[0];
    const float* w_attn     = (const float*)d_in[1];
    const float* b_attn     = (const float*)d_in[2];
    const float* w_proj     = (const float*)d_in[3];
    const float* b_proj     = (const float*)d_in[4];
    const float* w_fc       = (const float*)d_in[5];
    const float* b_fc       = (const float*)d_in[6];
    const float* w_mlp_proj = (const float*)d_in[7];
    const float* b_mlp_proj = (const float*)d_in[8];
    float* out = (float*)d_out;

    __half *ln_p, *y_p, *h_p, *w_p;
    float *x1_p;
    cudaGetSymbolAddress((void**)&ln_p, g_ln);
    cudaGetSymbolAddress((void**)&y_p,  g_y);
    cudaGetSymbolAddress((void**)&x1_p, g_x1);
    cudaGetSymbolAddress((void**)&h_p,  g_h);
    cudaGetSymbolAddress((void**)&w_p,  g_w);

    const int gemm_smem = 3 * 32768;   // 96KB
    const int attn_smem = 3 * 32768;   // 96KB
    cudaFuncSetAttribute(gemm_f16, cudaFuncAttributeMaxDynamicSharedMemorySize, gemm_smem);
    cudaFuncSetAttribute(attn_tc,  cudaFuncAttributeMaxDynamicSharedMemorySize, attn_smem);

    const int M1 = 1024*1024;
    cvtw_all<<<12*M1/1024, 256>>>(w_attn, w_proj, w_fc, w_mlp_proj, w_p);

    // 1. ln1
    ln_kernel<<<Md/8, 256>>>(x, ln_p);
    // 2. qkv (staged coalesced scatter -> g_q/g_kp/g_vp)
    gemm_f16<<<dim3(3072/128, Md/128), 256, gemm_smem>>>(ln_p, w_p, b_attn, nullptr,
                                                         nullptr, Md, 3072, 1024, 2);
    // 3. attention
    attn_tc<<<dim3(Td/128, 64), 256, attn_smem>>>(y_p);
    // 4. x1 = proj(y) + x (fp32)
    gemm_f16<<<dim3(1024/128, Md/128), 256, gemm_smem>>>(y_p, w_p + 3*M1, b_proj, x,
                                                         x1_p, Md, 1024, 1024, 0);
    // 5. ln2
    ln_kernel<<<Md/8, 256>>>(x1_p, ln_p);
    // 6. fc + gelu -> h (f16)
    gemm_f16<<<dim3(4096/128, Md/128), 256, gemm_smem>>>(ln_p, w_p + 4*M1, b_fc, nullptr,
                                                         h_p, Md, 4096, 1024, 1);
    // 7. out = mlp(h) + x1 (fp32)
    gemm_f16<<<dim3(1024/128, Md/128), 256, gemm_smem>>>(h_p, w_p + 8*M1, b_mlp_proj, x1_p,
                                                         out, Md, 1024, 4096, 0);
}

// round 17
// speedup vs baseline: 1.0247x; 1.0154x over previous
#include <cuda_runtime.h>
#include <cuda_fp16.h>
#include <cstdint>

#define Bd 4
#define Td 2048
#define Cd 1024
#define Md (Bd*Td)
#define QSC 0.18033688011112042f   // log2(e)/8

__device__ __half g_ln[Md*Cd];
__device__ __half g_y [Md*Cd];
__device__ float  g_x1[Md*Cd];
__device__ __half g_h [Md*4*Cd];
__device__ __half g_w [12*1024*1024];
__device__ __half g_q [64*Td*64];
__device__ __half g_kp[64*Td*64];
__device__ __half g_vp[64*Td*64];

__device__ __forceinline__ uint32_t packh(float lo, float hi){
    __half2 h = __floats2half2_rn(lo, hi);
    return *(uint32_t*)&h;
}
__device__ __forceinline__ uint32_t exp2u(uint32_t s){
    __half2 h = h2exp2(*(__half2*)&s);
    return *(uint32_t*)&h;
}
__device__ __forceinline__ float tanh_ap(float x){
    float r; asm("tanh.approx.f32 %0, %1;" : "=f"(r) : "f"(x)); return r;
}
__device__ __forceinline__ float gelu_f(float x){
    float u = 0.7978845608028654f * (x + 0.044715f * x * x * x);
    return 0.5f * x * (1.0f + tanh_ap(u));
}
__device__ __forceinline__ void cp_async16(void* smem, const void* gmem){
    uint32_t s = (uint32_t)__cvta_generic_to_shared(smem);
    asm volatile("cp.async.cg.shared.global [%0], [%1], 16;\n" :: "r"(s), "l"(gmem));
}
__device__ __forceinline__ void cp_commit(){ asm volatile("cp.async.commit_group;\n"); }
template<int N> __device__ __forceinline__ void cp_wait(){
    asm volatile("cp.async.wait_group %0;\n" :: "n"(N));
}
__device__ __forceinline__ void mma16h(float c[4], const uint32_t a[4],
                                       uint32_t b0, uint32_t b1){
    asm volatile("mma.sync.aligned.m16n8k16.row.col.f32.f16.f16.f32 "
      "{%0,%1,%2,%3},{%4,%5,%6,%7},{%8,%9},{%0,%1,%2,%3};"
      : "+f"(c[0]), "+f"(c[1]), "+f"(c[2]), "+f"(c[3])
      : "r"(a[0]), "r"(a[1]), "r"(a[2]), "r"(a[3]), "r"(b0), "r"(b1));
}
__device__ __forceinline__ void mma16hh(uint32_t c[2], const uint32_t a[4],
                                        uint32_t b0, uint32_t b1){
    asm volatile("mma.sync.aligned.m16n8k16.row.col.f16.f16.f16.f16 "
      "{%0,%1},{%2,%3,%4,%5},{%6,%7},{%0,%1};"
      : "+r"(c[0]), "+r"(c[1])
      : "r"(a[0]), "r"(a[1]), "r"(a[2]), "r"(a[3]), "r"(b0), "r"(b1));
}
__device__ __forceinline__ void ldsm4(uint32_t& r0, uint32_t& r1, uint32_t& r2,
                                      uint32_t& r3, uint32_t a){
    asm volatile("ldmatrix.sync.aligned.m8n8.x4.shared.b16 {%0,%1,%2,%3}, [%4];"
                 : "=r"(r0), "=r"(r1), "=r"(r2), "=r"(r3) : "r"(a));
}
__device__ __forceinline__ void ldsm4t(uint32_t& r0, uint32_t& r1, uint32_t& r2,
                                       uint32_t& r3, uint32_t a){
    asm volatile("ldmatrix.sync.aligned.m8n8.x4.trans.shared.b16 {%0,%1,%2,%3}, [%4];"
                 : "=r"(r0), "=r"(r1), "=r"(r2), "=r"(r3) : "r"(a));
}

// ---------------- weight conversion ----------------
__global__ __launch_bounds__(256) void cvtw_all(
    const float* __restrict__ wa, const float* __restrict__ wp,
    const float* __restrict__ wf, const float* __restrict__ wm,
    __half* __restrict__ d)
{
    const int M1 = 1024*1024;
    int i = (blockIdx.x * 256 + threadIdx.x) * 4;
    const float* s;
    int off;
    if      (i <  3*M1){ s = wa; off = 0;    }
    else if (i <  4*M1){ s = wp; off = 3*M1; }
    else if (i <  8*M1){ s = wf; off = 4*M1; }
    else               { s = wm; off = 8*M1; }
    float4 v = *(const float4*)(s + (i - off));
    *(uint2*)(d + i) = make_uint2(packh(v.x, v.y), packh(v.z, v.w));
}

// ---------------- LayerNorm: one warp per row ----------------
__global__ __launch_bounds__(256) void ln_kernel(const float* __restrict__ in,
                                                 __half* __restrict__ out){
    const int wid = threadIdx.x >> 5, lane = threadIdx.x & 31;
    const int row = blockIdx.x * 8 + wid;
    const float4* src = (const float4*)(in + (size_t)row * Cd);
    float4 v[8];
    float s = 0.f;
    #pragma unroll
    for (int i = 0; i < 8; i++){
        v[i] = src[i * 32 + lane];
        s += v[i].x + v[i].y + v[i].z + v[i].w;
    }
    #pragma unroll
    for (int o = 16; o > 0; o >>= 1) s += __shfl_xor_sync(~0u, s, o);
    float mean = s * (1.0f/1024.0f);
    float ss = 0.f;
    #pragma unroll
    for (int i = 0; i < 8; i++){
        v[i].x -= mean; v[i].y -= mean; v[i].z -= mean; v[i].w -= mean;
        ss += v[i].x*v[i].x + v[i].y*v[i].y + v[i].z*v[i].z + v[i].w*v[i].w;
    }
    #pragma unroll
    for (int o = 16; o > 0; o >>= 1) ss += __shfl_xor_sync(~0u, ss, o);
    float rstd = rsqrtf(ss * (1.0f/1024.0f) + 1e-10f);
    uint2* dst = (uint2*)(out + (size_t)row * Cd);
    #pragma unroll
    for (int i = 0; i < 8; i++)
        dst[i * 32 + lane] = make_uint2(packh(v[i].x*rstd, v[i].y*rstd),
                                        packh(v[i].z*rstd, v[i].w*rstd));
}

// ---------------- f16 GEMM (proven: modes 0/1/2) ----------------
__global__ __launch_bounds__(256) void gemm_f16(
    const __half* __restrict__ A, const __half* __restrict__ W,
    const float* __restrict__ bias, const float* __restrict__ res,
    void* outp, int M, int N, int K, int mode)
{
    extern __shared__ char smc[];
    const int bm = blockIdx.y * 128, bn = blockIdx.x * 128;
    const int tid = threadIdx.x, wid = tid >> 5, lane = tid & 31;
    const int wm = (wid >> 2) * 64, wn = (wid & 3) * 32;
    const int g = lane >> 2, tg = lane & 3;
    const int l7 = lane & 7, kc = (lane >> 3) & 1, hc = (lane >> 4) & 1;
    const uint32_t smb = (uint32_t)__cvta_generic_to_shared(smc);

    float acc[4][4][4];
    #pragma unroll
    for (int i = 0; i < 4; i++)
        #pragma unroll
        for (int j = 0; j < 4; j++)
            #pragma unroll
            for (int k = 0; k < 4; k++) acc[i][j][k] = 0.f;

    const int nt = K >> 6;
    auto load_st = [&](int kt, int st){
        char* base = smc + st * 32768;
        #pragma unroll
        for (int i = 0; i < 4; i++){
            int x = tid + i * 256;
            int r = x >> 3, pc = x & 7;
            int sw = ((pc ^ (r & 7)) << 4);
            cp_async16(base + r*128 + sw,         A + (size_t)(bm + r)*K + kt*64 + pc*8);
            cp_async16(base + 16384 + r*128 + sw, W + (size_t)(bn + r)*K + kt*64 + pc*8);
        }
    };

    load_st(0, 0); cp_commit();
    load_st(1, 1); cp_commit();

    for (int kt = 0; kt < nt; kt++){
        cp_wait<1>();
        __syncthreads();
        if (kt + 2 < nt){ load_st(kt + 2, (kt + 2) % 3); }
        cp_commit();
        const uint32_t sa = smb + (uint32_t)((kt % 3) * 32768);
        const uint32_t sb = sa + 16384;
        #pragma unroll
        for (int ks = 0; ks < 4; ks++){
            const uint32_t co = (uint32_t)(((2*ks + hc) ^ l7) << 4);
            uint32_t a[4][4];
            #pragma unroll
            for (int mf = 0; mf < 4; mf++)
                ldsm4(a[mf][0], a[mf][1], a[mf][2], a[mf][3],
                      sa + (uint32_t)((wm + mf*16 + l7 + 8*kc) * 128) + co);
            #pragma unroll
            for (int pr = 0; pr < 2; pr++){
                uint32_t r0, r1, r2, r3;
                ldsm4(r0, r1, r2, r3,
                      sb + (uint32_t)((wn + pr*16 + l7 + 8*kc) * 128) + co);
                #pragma unroll
                for (int mf = 0; mf < 4; mf++){
                    mma16h(acc[mf][2*pr  ], a[mf], r0, r2);
                    mma16h(acc[mf][2*pr+1], a[mf], r1, r3);
                }
            }
        }
    }

    if (mode == 2){
        __syncthreads();
        __half* stg = (__half*)smc;
        const float qsc = (bn < 1024) ? QSC : 1.0f;
        #pragma unroll
        for (int mf = 0; mf < 4; mf++){
            #pragma unroll
            for (int nf = 0; nf < 4; nf++){
                int rl = wm + mf * 16 + g;
                int cl = wn + nf * 8 + 2 * tg;
                int col = bn + cl;
                float bx = bias[col], by = bias[col + 1];
                *(uint32_t*)&stg[rl * 128 + cl] =
                    packh((acc[mf][nf][0] + bx) * qsc, (acc[mf][nf][1] + by) * qsc);
                *(uint32_t*)&stg[(rl + 8) * 128 + cl] =
                    packh((acc[mf][nf][2] + bx) * qsc, (acc[mf][nf][3] + by) * qsc);
            }
        }
        __syncthreads();
        #pragma unroll
        for (int i = 0; i < 8; i++){
            int x = tid + i * 256;
            int r = x >> 4, c16 = x & 15;
            uint4 v = ((const uint4*)stg)[x];
            int row = bm + r, t = row & 2047, b = row >> 11;
            int col = bn + c16 * 8;
            if (col < 1024){
                int h = col >> 6, d = col & 63;
                *(uint4*)(g_q + ((size_t)(b*16 + h)*Td + t)*64 + d) = v;
            } else if (col < 2048){
                int c2 = col - 1024, h = c2 >> 6, d = c2 & 63;
                int dc = (d >> 3) ^ (t & 7);
                *(uint4*)((char*)g_kp + ((size_t)(b*16 + h)*Td + t)*128 + dc*16) = v;
            } else {
                int c2 = col - 2048, h = c2 >> 6, d = c2 & 63;
                int dc = (d >> 3) ^ (t & 7);
                *(uint4*)((char*)g_vp + ((size_t)(b*16 + h)*Td + t)*128 + dc*16) = v;
            }
        }
        return;
    }

    #pragma unroll
    for (int mf = 0; mf < 4; mf++){
        #pragma unroll
        for (int nf = 0; nf < 4; nf++){
            int row = bm + wm + mf * 16 + g;
            int col = bn + wn + nf * 8 + 2 * tg;
            float bx = bias[col], by = bias[col + 1];
            float o0 = acc[mf][nf][0] + bx, o1 = acc[mf][nf][1] + by;
            float o2 = acc[mf][nf][2] + bx, o3 = acc[mf][nf][3] + by;
            if (mode == 0){
                if (res){
                    float2 r0 = *(const float2*)(res + (size_t)row * N + col);
                    float2 r1 = *(const float2*)(res + (size_t)(row + 8) * N + col);
                    o0 += r0.x; o1 += r0.y; o2 += r1.x; o3 += r1.y;
                }
                float* out = (float*)outp;
                *(float2*)(out + (size_t)row * N + col)       = make_float2(o0, o1);
                *(float2*)(out + (size_t)(row + 8) * N + col) = make_float2(o2, o3);
            } else {
                __half* out = (__half*)outp;
                *(uint32_t*)(out + (size_t)row * N + col)       = packh(gelu_f(o0), gelu_f(o1));
                *(uint32_t*)(out + (size_t)(row + 8) * N + col) = packh(gelu_f(o2), gelu_f(o3));
            }
        }
    }
}

// ---------------- Flash attention v9: 3-stage ring, single sync/tile -------
__global__ __launch_bounds__(256, 2) void attn_tc(__half* __restrict__ y){
    extern __shared__ char asm_[];            // 3 stages x (K 16KB + V 16KB)
    const int qt = (int)gridDim.x - 1 - (int)blockIdx.x;
    const int bh = blockIdx.y;
    const int b  = bh >> 4, h = bh & 15;
    const int q0 = qt * 128;
    const int tid = threadIdx.x, wid = tid >> 5, lane = tid & 31;
    const int g = lane >> 2, tg = lane & 3;
    const int wrow = wid * 16;
    const int l7 = lane & 7, kc = (lane >> 3) & 1, hc = (lane >> 4) & 1;
    const uint32_t smb = (uint32_t)__cvta_generic_to_shared(asm_);
    const uint32_t ONES = 0x3C003C00u;
    const uint32_t NINF_LO = 0x0000FBFFu;
    const uint32_t NINF_HI = 0xFBFF0000u;

    uint32_t aq[4][4];
    {
        const __half* q0p = g_q + ((size_t)bh*Td + q0 + wrow + g)*64;
        const __half* q1p = q0p + 8*64;
        #pragma unroll
        for (int kf = 0; kf < 4; kf++){
            aq[kf][0] = *(const uint32_t*)(q0p + kf*16 +     2*tg);
            aq[kf][1] = *(const uint32_t*)(q1p + kf*16 +     2*tg);
            aq[kf][2] = *(const uint32_t*)(q0p + kf*16 + 8 + 2*tg);
            aq[kf][3] = *(const uint32_t*)(q1p + kf*16 + 8 + 2*tg);
        }
    }

    float oacc[8][4];
    #pragma unroll
    for (int i = 0; i < 8; i++)
        #pragma unroll
        for (int j = 0; j < 4; j++) oacc[i][j] = 0.f;
    float lacc[4] = {0.f, 0.f, 0.f, 0.f};

    const char* kpb = (const char*)(g_kp + (size_t)bh * Td * 64);
    const char* vpb = (const char*)(g_vp + (size_t)bh * Td * 64);
    auto load_tile = [&](int kt2, int s){
        const char* ks = kpb + (size_t)kt2 * 16384;
        const char* vs = vpb + (size_t)kt2 * 16384;
        char* kd = asm_ + s * 32768;
        char* vd = kd + 16384;
        #pragma unroll
        for (int i = 0; i < 4; i++){
            int x = (tid + i * 256) * 16;
            cp_async16(kd + x, ks + x);
            cp_async16(vd + x, vs + x);
        }
    };

    const int nk2 = qt + 1;
    load_tile(0, 0); cp_commit();
    if (nk2 > 1){ load_tile(1, 1); } cp_commit();

    for (int kt2 = 0; kt2 < nk2; kt2++){
        cp_wait<1>();
        __syncthreads();
        if (kt2 + 2 < nk2){ load_tile(kt2 + 2, (kt2 + 2) % 3); }
        cp_commit();
        const uint32_t stgb = smb + (uint32_t)((kt2 % 3) * 32768);

        #pragma unroll
        for (int sub = 0; sub < 2; sub++){
            const int key0 = kt2 * 128 + sub * 64;
            if (key0 <= q0 + wrow + 15){
                const uint32_t kbuf = stgb + (uint32_t)(sub * 8192);
                const uint32_t vbuf = kbuf + 16384;

                uint32_t sacc16[8][2];
                #pragma unroll
                for (int i = 0; i < 8; i++){ sacc16[i][0] = 0; sacc16[i][1] = 0; }
                #pragma unroll
                for (int p = 0; p < 4; p++){
                    const uint32_t krb = kbuf + (uint32_t)((p*16 + 8*hc + l7) * 128);
                    #pragma unroll
                    for (int kf = 0; kf < 4; kf++){
                        uint32_t r0, r1, r2, r3;
                        ldsm4(r0, r1, r2, r3, krb + (uint32_t)(((2*kf + kc) ^ l7) << 4));
                        mma16hh(sacc16[2*p  ], aq[kf], r0, r1);
                        mma16hh(sacc16[2*p+1], aq[kf], r2, r3);
                    }
                }

                if (key0 + 63 > q0 + wrow){
                    const int row0 = q0 + wrow + g, row1 = row0 + 8;
                    #pragma unroll
                    for (int nf = 0; nf < 8; nf++){
                        int c0 = key0 + nf*8 + 2*tg, c1 = c0 + 1;
                        uint32_t v0 = sacc16[nf][0], v1 = sacc16[nf][1];
                        if (c0 > row0) v0 = (v0 & 0xFFFF0000u) | NINF_LO;
                        if (c1 > row0) v0 = (v0 & 0x0000FFFFu) | NINF_HI;
                        if (c0 > row1) v1 = (v1 & 0xFFFF0000u) | NINF_LO;
                        if (c1 > row1) v1 = (v1 & 0x0000FFFFu) | NINF_HI;
                        sacc16[nf][0] = v0; sacc16[nf][1] = v1;
                    }
                }

                uint32_t ap[4][4];
                #pragma unroll
                for (int kf = 0; kf < 4; kf++){
                    ap[kf][0] = exp2u(sacc16[2*kf  ][0]);
                    ap[kf][1] = exp2u(sacc16[2*kf  ][1]);
                    ap[kf][2] = exp2u(sacc16[2*kf+1][0]);
                    ap[kf][3] = exp2u(sacc16[2*kf+1][1]);
                }

                #pragma unroll
                for (int kf = 0; kf < 4; kf++){
                    mma16h(lacc, ap[kf], ONES, ONES);
                    const uint32_t vrb = vbuf + (uint32_t)((16*kf + l7 + 8*kc) * 128);
                    #pragma unroll
                    for (int p = 0; p < 4; p++){
                        uint32_t r0, r1, r2, r3;
                        ldsm4t(r0, r1, r2, r3, vrb + (uint32_t)(((2*p + hc) ^ l7) << 4));
                        mma16h(oacc[2*p  ], ap[kf], r0, r1);
                        mma16h(oacc[2*p+1], ap[kf], r2, r3);
                    }
                }
            }
        }
    }

    float inv0 = 1.0f / lacc[0], inv1 = 1.0f / lacc[2];
    __half* yb = y + ((size_t)(b*Td + q0)) * Cd + h * 64;
    #pragma unroll
    for (int nf = 0; nf < 8; nf++){
        int col = nf*8 + 2*tg;
        *(uint32_t*)(yb + (size_t)(wrow + g    ) * Cd + col) =
            packh(oacc[nf][0]*inv0, oacc[nf][1]*inv0);
        *(uint32_t*)(yb + (size_t)(wrow + g + 8) * Cd + col) =
            packh(oacc[nf][2]*inv1, oacc[nf][3]*inv1);
    }
}

// ---------------------------------------------------------------------------
extern "C" void kernel_launch(void* const* d_in, const int* in_sizes, int n_in,
                              void* d_out, int out_size){
    const float* x          = (const float*)d_in[0];
    const float* w_attn     = (const float*)d_in[1];
    const float* b_attn     = (const float*)d_in[2];
    const float* w_proj     = (const float*)d_in[3];
    const float* b_proj     = (const float*)d_in[4];
    const float* w_fc       = (const float*)d_in[5];
    const float* b_fc       = (const float*)d_in[6];
    const float* w_mlp_proj = (const float*)d_in[7];
    const float* b_mlp_proj = (const float*)d_in[8];
    float* out = (float*)d_out;

    __half *ln_p, *y_p, *h_p, *w_p;
    float *x1_p;
    cudaGetSymbolAddress((void**)&ln_p, g_ln);
    cudaGetSymbolAddress((void**)&y_p,  g_y);
    cudaGetSymbolAddress((void**)&x1_p, g_x1);
    cudaGetSymbolAddress((void**)&h_p,  g_h);
    cudaGetSymbolAddress((void**)&w_p,  g_w);

    const int gemm_smem = 3 * 32768;   // 96KB
    const int attn_smem = 3 * 32768;   // 96KB
    cudaFuncSetAttribute(gemm_f16, cudaFuncAttributeMaxDynamicSharedMemorySize, gemm_smem);
    cudaFuncSetAttribute(attn_tc,  cudaFuncAttributeMaxDynamicSharedMemorySize, attn_smem);

    const int M1 = 1024*1024;
    cvtw_all<<<12*M1/1024, 256>>>(w_attn, w_proj, w_fc, w_mlp_proj, w_p);

    // 1. ln1
    ln_kernel<<<Md/8, 256>>>(x, ln_p);
    // 2. qkv (staged coalesced scatter -> g_q/g_kp/g_vp)
    gemm_f16<<<dim3(3072/128, Md/128), 256, gemm_smem>>>(ln_p, w_p, b_attn, nullptr,
                                                         nullptr, Md, 3072, 1024, 2);
    // 3. attention
    attn_tc<<<dim3(Td/128, 64), 256, attn_smem>>>(y_p);
    // 4. x1 = proj(y) + x (fp32)
    gemm_f16<<<dim3(1024/128, Md/128), 256, gemm_smem>>>(y_p, w_p + 3*M1, b_proj, x,
                                                         x1_p, Md, 1024, 1024, 0);
    // 5. ln2
    ln_kernel<<<Md/8, 256>>>(x1_p, ln_p);
    // 6. fc + gelu -> h (f16)
    gemm_f16<<<dim3(4096/128, Md/128), 256, gemm_smem>>>(ln_p, w_p + 4*M1, b_fc, nullptr,
                                                         h_p, Md, 4096, 1024, 1);
    // 7. out = mlp(h) + x1 (fp32)
    gemm_f16<<<dim3(1024/128, Md/128), 256, gemm_smem>>>(h_p, w_p + 8*M1, b_mlp_proj, x1_p,
                                                         out, Md, 1024, 4096, 0);
}